// round 1
// baseline (speedup 1.0000x reference)
#include <cuda_runtime.h>
#include <cuda_bf16.h>
#include <cstdint>

// Problem constants
#define BB 2
#define SS 4096
#define DD 2048
#define HQ 32
#define HK 8
#define HH 32
#define DK 64
#define DV 64
#define OUT_D 2048
#define QKV 3072
#define NC 64          // number of chunks (S / CHUNK)
#define CH 64          // chunk size

// ---------------- scratch (device globals; no allocation allowed) ----------
__device__ float g_proj[(size_t)BB * SS * QKV];          // 96 MB
__device__ float g_o[(size_t)BB * SS * (HH * DV)];       // 64 MB
__device__ float g_kv[(size_t)BB * HK * NC * DK * DV];   // 16 MB  per-chunk K^T V
__device__ float g_scum[(size_t)BB * HK * NC * DK * DV]; // 16 MB  exclusive prefix
__device__ float g_stot[(size_t)BB * HK * DK * DV];      // 256 KB total sum

// ---------------------------------------------------------------------------
// SGEMM: C[M,N] = A[M,K] * B[K,N], all row-major, M%128==0, N%128==0, K%8==0
// 128x128 block tile, BK=8, 256 threads, 8x8 per-thread microtile,
// double-buffered SMEM with register prefetch.
// ---------------------------------------------------------------------------
__global__ __launch_bounds__(256, 2)
void sgemm128(const float* __restrict__ A, const float* __restrict__ B,
              float* __restrict__ C, int M, int N, int K) {
    __shared__ float As[2][8][128];
    __shared__ float Bs[2][8][128];

    const int tid = threadIdx.x;
    const int tx = tid & 15;        // 0..15 -> N microtile
    const int ty = tid >> 4;        // 0..15 -> M microtile
    const int bm = blockIdx.y * 128;
    const int bn = blockIdx.x * 128;

    const int aRow = tid >> 1;          // 0..127
    const int aCol = (tid & 1) << 2;    // 0 or 4
    const int bRow = tid >> 5;          // 0..7
    const int bCol = (tid & 31) << 2;   // 0..124

    const float* Ap = A + (size_t)(bm + aRow) * K + aCol;
    const float* Bp = B + (size_t)bRow * N + bn + bCol;

    // first tile
    float4 a4 = *(const float4*)Ap;
    float4 b4 = *(const float4*)Bp;
    As[0][aCol + 0][aRow] = a4.x;
    As[0][aCol + 1][aRow] = a4.y;
    As[0][aCol + 2][aRow] = a4.z;
    As[0][aCol + 3][aRow] = a4.w;
    *(float4*)&Bs[0][bRow][bCol] = b4;
    __syncthreads();

    float acc[8][8];
#pragma unroll
    for (int i = 0; i < 8; i++)
#pragma unroll
        for (int j = 0; j < 8; j++) acc[i][j] = 0.f;

    const int nt = K >> 3;
    for (int t = 0; t < nt; t++) {
        const int cur = t & 1;
        if (t + 1 < nt) {
            a4 = *(const float4*)(Ap + (size_t)(t + 1) * 8);
            b4 = *(const float4*)(Bp + (size_t)(t + 1) * 8 * N);
        }
#pragma unroll
        for (int kk = 0; kk < 8; kk++) {
            float ar[8], br[8];
            float4 t0 = *(const float4*)&As[cur][kk][ty * 8];
            float4 t1 = *(const float4*)&As[cur][kk][ty * 8 + 4];
            ar[0] = t0.x; ar[1] = t0.y; ar[2] = t0.z; ar[3] = t0.w;
            ar[4] = t1.x; ar[5] = t1.y; ar[6] = t1.z; ar[7] = t1.w;
            float4 u0 = *(const float4*)&Bs[cur][kk][tx * 8];
            float4 u1 = *(const float4*)&Bs[cur][kk][tx * 8 + 4];
            br[0] = u0.x; br[1] = u0.y; br[2] = u0.z; br[3] = u0.w;
            br[4] = u1.x; br[5] = u1.y; br[6] = u1.z; br[7] = u1.w;
#pragma unroll
            for (int i = 0; i < 8; i++)
#pragma unroll
                for (int j = 0; j < 8; j++)
                    acc[i][j] = fmaf(ar[i], br[j], acc[i][j]);
        }
        if (t + 1 < nt) {
            const int nxt = cur ^ 1;
            As[nxt][aCol + 0][aRow] = a4.x;
            As[nxt][aCol + 1][aRow] = a4.y;
            As[nxt][aCol + 2][aRow] = a4.z;
            As[nxt][aCol + 3][aRow] = a4.w;
            *(float4*)&Bs[nxt][bRow][bCol] = b4;
            __syncthreads();
        }
    }

    float* Cp = C + (size_t)(bm + ty * 8) * N + bn + tx * 8;
#pragma unroll
    for (int i = 0; i < 8; i++) {
        *(float4*)(Cp + (size_t)i * N) =
            make_float4(acc[i][0], acc[i][1], acc[i][2], acc[i][3]);
        *(float4*)(Cp + (size_t)i * N + 4) =
            make_float4(acc[i][4], acc[i][5], acc[i][6], acc[i][7]);
    }
}

// ---------------------------------------------------------------------------
// Phase A: per-chunk KV[b,hk,c][d][e] = sum_j k[j][d] * v[j][e]
// grid = (NC, HK, B), 256 threads, 4x4 per-thread microtile of 64x64 output.
// ---------------------------------------------------------------------------
__global__ __launch_bounds__(256)
void kv_kernel(const float* __restrict__ proj, float* __restrict__ kv) {
    const int c = blockIdx.x, hk = blockIdx.y, b = blockIdx.z;
    __shared__ float ks[64][64];
    __shared__ float vs[64][64];
    const int tid = threadIdx.x;

    const float* kb = proj + (size_t)(b * SS + c * CH) * QKV + HQ * DK + hk * DK;
    const float* vb = kb + HK * DK;   // v block starts 512 after k block

    for (int t = tid; t < 1024; t += 256) {
        const int r = t >> 4, c4 = (t & 15) << 2;
        *(float4*)&ks[r][c4] = *(const float4*)(kb + (size_t)r * QKV + c4);
        *(float4*)&vs[r][c4] = *(const float4*)(vb + (size_t)r * QKV + c4);
    }
    __syncthreads();

    const int tx = tid & 15, ty = tid >> 4;
    const int d0 = ty * 4, e0 = tx * 4;
    float acc[4][4];
#pragma unroll
    for (int i = 0; i < 4; i++)
#pragma unroll
        for (int j = 0; j < 4; j++) acc[i][j] = 0.f;

    for (int j = 0; j < 64; j++) {
        float kr[4], vr[4];
#pragma unroll
        for (int i = 0; i < 4; i++) kr[i] = ks[j][d0 + i];
#pragma unroll
        for (int e = 0; e < 4; e++) vr[e] = vs[j][e0 + e];
#pragma unroll
        for (int i = 0; i < 4; i++)
#pragma unroll
            for (int e = 0; e < 4; e++)
                acc[i][e] = fmaf(kr[i], vr[e], acc[i][e]);
    }

    float* dst = kv + ((size_t)((b * HK + hk) * NC + c)) * (DK * DV);
#pragma unroll
    for (int i = 0; i < 4; i++)
        *(float4*)(dst + (size_t)(d0 + i) * DV + e0) =
            make_float4(acc[i][0], acc[i][1], acc[i][2], acc[i][3]);
}

// ---------------------------------------------------------------------------
// Phase B: exclusive prefix sum of KV over chunks, per (b,hk).
// grid = B*HK = 16 blocks, 256 threads, each thread owns 16 state elements.
// Also writes the total sum (for the final state).
// ---------------------------------------------------------------------------
__global__ __launch_bounds__(256)
void scan_kernel(const float* __restrict__ kv, float* __restrict__ scum,
                 float* __restrict__ stot) {
    const int bh = blockIdx.x;
    const int tid = threadIdx.x;
    float run[16];
#pragma unroll
    for (int i = 0; i < 16; i++) run[i] = 0.f;

    const size_t base = (size_t)bh * NC * (DK * DV);
    for (int c = 0; c < NC; c++) {
        const size_t off = base + (size_t)c * (DK * DV);
#pragma unroll
        for (int i = 0; i < 16; i++) {
            const int idx = i * 256 + tid;
            scum[off + idx] = run[i];
            run[i] += kv[off + idx];
        }
    }
    const size_t tb = (size_t)bh * (DK * DV);
#pragma unroll
    for (int i = 0; i < 16; i++) stot[tb + i * 256 + tid] = run[i];
}

// ---------------------------------------------------------------------------
// Phase C: per-chunk output.
//   o = tril(q k^T) v + q (S0[h] + Scum[hk,c])
// grid = (NC, H, B), 256 threads, dynamic SMEM 49408 B.
// ---------------------------------------------------------------------------
__global__ __launch_bounds__(256)
void attn_kernel(const float* __restrict__ proj, const float* __restrict__ s0,
                 const float* __restrict__ scum, float* __restrict__ o) {
    extern __shared__ float sm[];
    float* qs  = sm;            // [64][64] q
    float* SA  = sm + 4096;     // [64][64] S, then A
    float* kvp = sm + 8192;     // [64][65] k, then v (padded pitch 65)

    const int c = blockIdx.x, h = blockIdx.y, b = blockIdx.z;
    const int hk = h >> 2;
    const int tid = threadIdx.x;
    const int tx = tid & 15, ty = tid >> 4;
    const int row0 = ty * 4, col0 = tx * 4;

    const float* qb  = proj + (size_t)(b * SS + c * CH) * QKV + h * DK;
    const float* kb  = proj + (size_t)(b * SS + c * CH) * QKV + HQ * DK + hk * DK;
    const float* vb  = kb + HK * DK;
    const float* s0b = s0 + (size_t)(b * HH + h) * (DK * DV);
    const float* scb = scum + (size_t)((b * HK + hk) * NC + c) * (DK * DV);

    // load q and S = S0 + Scum
    for (int t = tid; t < 1024; t += 256) {
        const int r = t >> 4, c4 = (t & 15) << 2;
        *(float4*)&qs[r * 64 + c4] = *(const float4*)(qb + (size_t)r * QKV + c4);
        float4 u = *(const float4*)(s0b + r * 64 + c4);
        float4 w = *(const float4*)(scb + r * 64 + c4);
        u.x += w.x; u.y += w.y; u.z += w.z; u.w += w.w;
        *(float4*)&SA[r * 64 + c4] = u;
    }
    __syncthreads();

    float acc[4][4];
#pragma unroll
    for (int i = 0; i < 4; i++)
#pragma unroll
        for (int j = 0; j < 4; j++) acc[i][j] = 0.f;

    // acc += q @ S
    for (int d = 0; d < 64; d++) {
        float qr[4], sr[4];
#pragma unroll
        for (int i = 0; i < 4; i++) qr[i] = qs[(row0 + i) * 64 + d];
#pragma unroll
        for (int j = 0; j < 4; j++) sr[j] = SA[d * 64 + col0 + j];
#pragma unroll
        for (int i = 0; i < 4; i++)
#pragma unroll
            for (int j = 0; j < 4; j++)
                acc[i][j] = fmaf(qr[i], sr[j], acc[i][j]);
    }

    // load k (pitch 65) — no thread reads S anymore after the next barrier
    for (int t = tid; t < 1024; t += 256) {
        const int r = t >> 4, c4 = (t & 15) << 2;
        float4 u = *(const float4*)(kb + (size_t)r * QKV + c4);
        kvp[r * 65 + c4 + 0] = u.x;
        kvp[r * 65 + c4 + 1] = u.y;
        kvp[r * 65 + c4 + 2] = u.z;
        kvp[r * 65 + c4 + 3] = u.w;
    }
    __syncthreads();

    // A = tril(q k^T) into SA (overwrites S; safe: all q@S reads done)
    {
        float a[4][4];
#pragma unroll
        for (int i = 0; i < 4; i++)
#pragma unroll
            for (int j = 0; j < 4; j++) a[i][j] = 0.f;
        for (int d = 0; d < 64; d++) {
            float qr[4], kr[4];
#pragma unroll
            for (int i = 0; i < 4; i++) qr[i] = qs[(row0 + i) * 64 + d];
#pragma unroll
            for (int j = 0; j < 4; j++) kr[j] = kvp[(col0 + j) * 65 + d];
#pragma unroll
            for (int i = 0; i < 4; i++)
#pragma unroll
                for (int j = 0; j < 4; j++)
                    a[i][j] = fmaf(qr[i], kr[j], a[i][j]);
        }
#pragma unroll
        for (int i = 0; i < 4; i++)
#pragma unroll
            for (int j = 0; j < 4; j++)
                SA[(row0 + i) * 64 + col0 + j] =
                    (col0 + j <= row0 + i) ? a[i][j] : 0.f;
    }
    __syncthreads();

    // load v into kvp (overwrites k; safe after barrier)
    for (int t = tid; t < 1024; t += 256) {
        const int r = t >> 4, c4 = (t & 15) << 2;
        float4 u = *(const float4*)(vb + (size_t)r * QKV + c4);
        kvp[r * 65 + c4 + 0] = u.x;
        kvp[r * 65 + c4 + 1] = u.y;
        kvp[r * 65 + c4 + 2] = u.z;
        kvp[r * 65 + c4 + 3] = u.w;
    }
    __syncthreads();

    // acc += A @ v
    for (int j = 0; j < 64; j++) {
        float ar[4], vr[4];
#pragma unroll
        for (int i = 0; i < 4; i++) ar[i] = SA[(row0 + i) * 64 + j];
#pragma unroll
        for (int e = 0; e < 4; e++) vr[e] = kvp[j * 65 + col0 + e];
#pragma unroll
        for (int i = 0; i < 4; i++)
#pragma unroll
            for (int e = 0; e < 4; e++)
                acc[i][e] = fmaf(ar[i], vr[e], acc[i][e]);
    }

    float* ob = o + (size_t)(b * SS + c * CH) * (HH * DV) + h * DV;
#pragma unroll
    for (int i = 0; i < 4; i++)
        *(float4*)(ob + (size_t)(row0 + i) * (HH * DV) + col0) =
            make_float4(acc[i][0], acc[i][1], acc[i][2], acc[i][3]);
}

// ---------------------------------------------------------------------------
// Final state: Sf[b,h] = S0[b,h] + sum_c KV[b, h/4, c]
// ---------------------------------------------------------------------------
__global__ __launch_bounds__(256)
void final_state_kernel(const float* __restrict__ s0,
                        const float* __restrict__ stot,
                        float* __restrict__ out_tail) {
    const int idx = blockIdx.x * 256 + threadIdx.x;   // 0 .. 262143
    const int b = idx >> 17;
    const int rem = idx & 131071;
    const int h = rem >> 12;
    const int de = rem & 4095;
    out_tail[idx] = s0[idx] + stot[(size_t)(b * HK + (h >> 2)) * 4096 + de];
}

// ---------------------------------------------------------------------------
extern "C" void kernel_launch(void* const* d_in, const int* in_sizes, int n_in,
                              void* d_out, int out_size) {
    const float* x     = (const float*)d_in[0];   // [B,S,D]
    const float* s0    = (const float*)d_in[1];   // [B,H*DK*DV]
    const float* w_in  = (const float*)d_in[2];   // [D,QKV]
    const float* w_out = (const float*)d_in[3];   // [H*DV,OUT]
    float* out = (float*)d_out;

    float *proj, *o, *kv, *scum, *stot;
    cudaGetSymbolAddress((void**)&proj, g_proj);
    cudaGetSymbolAddress((void**)&o,    g_o);
    cudaGetSymbolAddress((void**)&kv,   g_kv);
    cudaGetSymbolAddress((void**)&scum, g_scum);
    cudaGetSymbolAddress((void**)&stot, g_stot);

    const dim3 blk(256);

    // 1) proj = x @ W_in : [8192,2048] x [2048,3072]
    sgemm128<<<dim3(QKV / 128, (BB * SS) / 128), blk>>>(x, w_in, proj,
                                                        BB * SS, QKV, DD);

    // 2) per-chunk KV
    kv_kernel<<<dim3(NC, HK, BB), blk>>>(proj, kv);

    // 3) exclusive prefix scan over chunks
    scan_kernel<<<dim3(BB * HK), blk>>>(kv, scum, stot);

    // 4) per-chunk outputs (dynamic smem 49408 B)
    cudaFuncSetAttribute(attn_kernel,
                         cudaFuncAttributeMaxDynamicSharedMemorySize, 49408);
    attn_kernel<<<dim3(NC, HH, BB), blk, 49408>>>(proj, s0, scum, o);

    // 5) out = o @ W_out : [8192,2048] x [2048,2048]  -> start of d_out
    sgemm128<<<dim3(OUT_D / 128, (BB * SS) / 128), blk>>>(o, w_out, out,
                                                          BB * SS, OUT_D,
                                                          HH * DV);

    // 6) final state -> tail of d_out
    final_state_kernel<<<dim3((BB * HH * DK * DV) / 256), blk>>>(
        s0, stot, out + (size_t)BB * SS * OUT_D);
}

// round 3
// speedup vs baseline: 2.7747x; 2.7747x over previous
#include <cuda_runtime.h>
#include <cuda_bf16.h>
#include <cstdint>

// Problem constants
#define BB 2
#define SS 4096
#define DD 2048
#define HQ 32
#define HK 8
#define HH 32
#define DK 64
#define DV 64
#define OUT_D 2048
#define QKV 3072
#define NC 64          // number of chunks (S / CHUNK)
#define CH 64          // chunk size

// GEMM tiling (mma.sync path)
#define BM 128
#define BN 128
#define BK 32
#define STAGES 4
#define SA_BYTES (BM * BK * 2)                  // 8192
#define SB_BYTES (BN * BK * 2)                  // 8192
#define STG_BYTES (2 * SA_BYTES + 2 * SB_BYTES) // 32768 (Ah, Al, Bh, Bl)
#define MMA_SMEM (STAGES * STG_BYTES)           // 131072

// ---------------- scratch (device globals; no allocation allowed) ----------
__device__ float g_proj[(size_t)BB * SS * QKV];            // 96 MB fp32
__device__ float g_kv[(size_t)BB * HK * NC * DK * DV];     // 16 MB
__device__ float g_scum[(size_t)BB * HK * NC * DK * DV];   // 16 MB
__device__ float g_stot[(size_t)BB * HK * DK * DV];        // 256 KB
__device__ __align__(256) __nv_bfloat16 g_x_hi[(size_t)BB * SS * DD];
__device__ __align__(256) __nv_bfloat16 g_x_lo[(size_t)BB * SS * DD];
__device__ __align__(256) __nv_bfloat16 g_winT_hi[(size_t)QKV * DD];   // [N,K]
__device__ __align__(256) __nv_bfloat16 g_winT_lo[(size_t)QKV * DD];
__device__ __align__(256) __nv_bfloat16 g_woutT_hi[(size_t)OUT_D * (HH * DV)];
__device__ __align__(256) __nv_bfloat16 g_woutT_lo[(size_t)OUT_D * (HH * DV)];
__device__ __align__(256) __nv_bfloat16 g_o_hi[(size_t)BB * SS * (HH * DV)];
__device__ __align__(256) __nv_bfloat16 g_o_lo[(size_t)BB * SS * (HH * DV)];

// ---------------------------------------------------------------------------
// PTX helpers (all plain sm_80-level: valid on .target sm_103)
// ---------------------------------------------------------------------------
__device__ __forceinline__ uint32_t smem_u32(const void* p) {
    uint32_t a;
    asm("{ .reg .u64 t; cvta.to.shared.u64 t, %1; cvt.u32.u64 %0, t; }"
        : "=r"(a) : "l"(p));
    return a;
}
__device__ __forceinline__ void cp_async16(uint32_t dst, const void* src) {
    asm volatile("cp.async.cg.shared.global [%0], [%1], 16;"
                 :: "r"(dst), "l"(src) : "memory");
}
__device__ __forceinline__ void cp_commit() {
    asm volatile("cp.async.commit_group;" ::: "memory");
}
template <int N>
__device__ __forceinline__ void cp_wait() {
    asm volatile("cp.async.wait_group %0;" :: "n"(N) : "memory");
}
__device__ __forceinline__ void ldsm4(uint32_t* r, uint32_t addr) {
    asm volatile("ldmatrix.sync.aligned.m8n8.x4.shared.b16 {%0,%1,%2,%3}, [%4];"
                 : "=r"(r[0]), "=r"(r[1]), "=r"(r[2]), "=r"(r[3]) : "r"(addr));
}
__device__ __forceinline__ void mma16816(float* d, const uint32_t* a,
                                         uint32_t b0, uint32_t b1) {
    asm volatile(
        "mma.sync.aligned.m16n8k16.row.col.f32.bf16.bf16.f32 "
        "{%0,%1,%2,%3}, {%4,%5,%6,%7}, {%8,%9}, {%0,%1,%2,%3};"
        : "+f"(d[0]), "+f"(d[1]), "+f"(d[2]), "+f"(d[3])
        : "r"(a[0]), "r"(a[1]), "r"(a[2]), "r"(a[3]), "r"(b0), "r"(b1));
}
// 64-byte rows; swizzle 16B slot within 128B window by (row>>1)&7
__device__ __forceinline__ uint32_t swz(uint32_t off) {
    return off ^ (((off >> 7) & 7) << 4);
}

// ---------------------------------------------------------------------------
// split helpers
// ---------------------------------------------------------------------------
__device__ __forceinline__ void split2(float v, __nv_bfloat16& h, __nv_bfloat16& l) {
    h = __float2bfloat16(v);
    l = __float2bfloat16(v - __bfloat162float(h));
}

// elementwise fp32 -> (hi, lo) bf16
__global__ __launch_bounds__(256)
void convert_split(const float4* __restrict__ src, __nv_bfloat162* __restrict__ hi,
                   __nv_bfloat162* __restrict__ lo, int n4) {
    for (int i = blockIdx.x * 256 + threadIdx.x; i < n4; i += gridDim.x * 256) {
        float4 v = src[i];
        __nv_bfloat16 h0, h1, h2, h3, l0, l1, l2, l3;
        split2(v.x, h0, l0); split2(v.y, h1, l1);
        split2(v.z, h2, l2); split2(v.w, h3, l3);
        hi[i * 2 + 0] = __halves2bfloat162(h0, h1);
        hi[i * 2 + 1] = __halves2bfloat162(h2, h3);
        lo[i * 2 + 0] = __halves2bfloat162(l0, l1);
        lo[i * 2 + 1] = __halves2bfloat162(l2, l3);
    }
}

// W[K][N] fp32 -> T_hi/T_lo [N][K] bf16 (tiled transpose)
__global__ __launch_bounds__(256)
void transpose_split(const float* __restrict__ W, __nv_bfloat16* __restrict__ Th,
                     __nv_bfloat16* __restrict__ Tl, int K, int N) {
    __shared__ float t[32][33];
    const int n0 = blockIdx.x * 32, k0 = blockIdx.y * 32;
    const int tx = threadIdx.x, ty = threadIdx.y;  // (32, 8)
    for (int i = ty; i < 32; i += 8)
        t[i][tx] = W[(size_t)(k0 + i) * N + n0 + tx];
    __syncthreads();
    for (int a = ty; a < 32; a += 8) {
        float v = t[tx][a];
        __nv_bfloat16 h, l;
        split2(v, h, l);
        Th[(size_t)(n0 + a) * K + k0 + tx] = h;
        Tl[(size_t)(n0 + a) * K + k0 + tx] = l;
    }
}

// ---------------------------------------------------------------------------
// Split-bf16 3-pass GEMM via mma.sync:
//   C[M,N] = A*B  with  A = Ah + Al ([M,K] row-major bf16),
//   B given transposed as Bt = Bh/Bl [N,K] row-major bf16.
//   C += Ah*Bh + Ah*Bl + Al*Bh  (Al*Bl dropped, ~2^-16 relative)
// CTA 128x128, BK=32, 8 warps (warp tile 64x32), 4-stage cp.async pipeline.
// ---------------------------------------------------------------------------
__global__ __launch_bounds__(256, 1)
void gemm_mma(const __nv_bfloat16* __restrict__ Ah,
              const __nv_bfloat16* __restrict__ Al,
              const __nv_bfloat16* __restrict__ Bh,
              const __nv_bfloat16* __restrict__ Bl,
              float* __restrict__ C, int M, int N, int K) {
    extern __shared__ char smem[];
    const uint32_t sb = smem_u32(smem);
    const int tid = threadIdx.x;
    const int warp = tid >> 5, lane = tid & 31;
    const int wm = warp >> 2;       // 0..1: 64-row slab
    const int wn = warp & 3;        // 0..3: 32-col slab
    const int bm = blockIdx.y * BM;
    const int bn = blockIdx.x * BN;

    float acc[4][4][4];             // [m16 tile][n8 tile][frag]
#pragma unroll
    for (int i = 0; i < 4; i++)
#pragma unroll
        for (int j = 0; j < 4; j++)
#pragma unroll
            for (int k = 0; k < 4; k++) acc[i][j][k] = 0.f;

    // stage loader: 512 16B transfers per matrix over 2 iterations
    auto load_stage = [&](int t, int s) {
        const uint32_t base = sb + s * STG_BYTES;
        const int k0 = t * BK;
#pragma unroll
        for (int i = 0; i < 2; i++) {
            const int idx = tid + i * 256;
            const int r = idx >> 2, c = idx & 3;
            const uint32_t off = swz((uint32_t)(r * 64 + c * 16));
            const size_t g = (size_t)r * K + k0 + c * 8;
            cp_async16(base + off, Ah + (size_t)bm * K + g);
            cp_async16(base + SA_BYTES + off, Al + (size_t)bm * K + g);
            cp_async16(base + 2 * SA_BYTES + off, Bh + (size_t)bn * K + g);
            cp_async16(base + 2 * SA_BYTES + SB_BYTES + off, Bl + (size_t)bn * K + g);
        }
    };

#pragma unroll
    for (int s = 0; s < STAGES - 1; s++) { load_stage(s, s); cp_commit(); }

    const int nt = K / BK;
    for (int t = 0; t < nt; t++) {
        cp_wait<STAGES - 2>();
        __syncthreads();
        if (t + STAGES - 1 < nt) load_stage(t + STAGES - 1, (t + STAGES - 1) & 3);
        cp_commit();

        const uint32_t base = sb + (t & 3) * STG_BYTES;
        const uint32_t ahB = base;
        const uint32_t alB = base + SA_BYTES;
        const uint32_t bhB = base + 2 * SA_BYTES;
        const uint32_t blB = bhB + SB_BYTES;

#pragma unroll
        for (int kk = 0; kk < 2; kk++) {
            uint32_t ah[4][4], al[4][4], bh[2][4], bl[2][4];
#pragma unroll
            for (int mt = 0; mt < 4; mt++) {
                const int row = wm * 64 + mt * 16 + (lane & 15);
                const uint32_t off =
                    swz((uint32_t)(row * 64 + kk * 32 + ((lane >> 4) & 1) * 16));
                ldsm4(ah[mt], ahB + off);
                ldsm4(al[mt], alB + off);
            }
#pragma unroll
            for (int nt2 = 0; nt2 < 2; nt2++) {
                const int row = wn * 32 + nt2 * 16 + ((lane >> 4) & 1) * 8 + (lane & 7);
                const uint32_t off =
                    swz((uint32_t)(row * 64 + kk * 32 + ((lane >> 3) & 1) * 16));
                ldsm4(bh[nt2], bhB + off);
                ldsm4(bl[nt2], blB + off);
            }
#pragma unroll
            for (int mt = 0; mt < 4; mt++) {
#pragma unroll
                for (int nt2 = 0; nt2 < 2; nt2++) {
                    mma16816(acc[mt][nt2 * 2],     ah[mt], bh[nt2][0], bh[nt2][1]);
                    mma16816(acc[mt][nt2 * 2 + 1], ah[mt], bh[nt2][2], bh[nt2][3]);
                    mma16816(acc[mt][nt2 * 2],     ah[mt], bl[nt2][0], bl[nt2][1]);
                    mma16816(acc[mt][nt2 * 2 + 1], ah[mt], bl[nt2][2], bl[nt2][3]);
                    mma16816(acc[mt][nt2 * 2],     al[mt], bh[nt2][0], bh[nt2][1]);
                    mma16816(acc[mt][nt2 * 2 + 1], al[mt], bh[nt2][2], bh[nt2][3]);
                }
            }
        }
    }

    // epilogue: direct global stores (float2 per fragment row)
#pragma unroll
    for (int mt = 0; mt < 4; mt++) {
        const int row = bm + wm * 64 + mt * 16 + (lane >> 2);
#pragma unroll
        for (int n8 = 0; n8 < 4; n8++) {
            const int col = bn + wn * 32 + n8 * 8 + ((lane & 3) << 1);
            *(float2*)&C[(size_t)row * N + col] =
                make_float2(acc[mt][n8][0], acc[mt][n8][1]);
            *(float2*)&C[(size_t)(row + 8) * N + col] =
                make_float2(acc[mt][n8][2], acc[mt][n8][3]);
        }
    }
}

// ---------------------------------------------------------------------------
// Phase A: per-chunk KV[b,hk,c][d][e] = sum_j k[j][d] * v[j][e]
// ---------------------------------------------------------------------------
__global__ __launch_bounds__(256)
void kv_kernel(const float* __restrict__ proj, float* __restrict__ kv) {
    const int c = blockIdx.x, hk = blockIdx.y, b = blockIdx.z;
    __shared__ float ks[64][64];
    __shared__ float vs[64][64];
    const int tid = threadIdx.x;

    const float* kb = proj + (size_t)(b * SS + c * CH) * QKV + HQ * DK + hk * DK;
    const float* vb = kb + HK * DK;

    for (int t = tid; t < 1024; t += 256) {
        const int r = t >> 4, c4 = (t & 15) << 2;
        *(float4*)&ks[r][c4] = *(const float4*)(kb + (size_t)r * QKV + c4);
        *(float4*)&vs[r][c4] = *(const float4*)(vb + (size_t)r * QKV + c4);
    }
    __syncthreads();

    const int tx = tid & 15, ty = tid >> 4;
    const int d0 = ty * 4, e0 = tx * 4;
    float acc[4][4];
#pragma unroll
    for (int i = 0; i < 4; i++)
#pragma unroll
        for (int j = 0; j < 4; j++) acc[i][j] = 0.f;

    for (int j = 0; j < 64; j++) {
        float kr[4], vr[4];
#pragma unroll
        for (int i = 0; i < 4; i++) kr[i] = ks[j][d0 + i];
#pragma unroll
        for (int e = 0; e < 4; e++) vr[e] = vs[j][e0 + e];
#pragma unroll
        for (int i = 0; i < 4; i++)
#pragma unroll
            for (int e = 0; e < 4; e++)
                acc[i][e] = fmaf(kr[i], vr[e], acc[i][e]);
    }

    float* dst = kv + ((size_t)((b * HK + hk) * NC + c)) * (DK * DV);
#pragma unroll
    for (int i = 0; i < 4; i++)
        *(float4*)(dst + (size_t)(d0 + i) * DV + e0) =
            make_float4(acc[i][0], acc[i][1], acc[i][2], acc[i][3]);
}

// ---------------------------------------------------------------------------
// Phase B: exclusive prefix sum of KV over chunks, per (b,hk).
// ---------------------------------------------------------------------------
__global__ __launch_bounds__(256)
void scan_kernel(const float* __restrict__ kv, float* __restrict__ scum,
                 float* __restrict__ stot) {
    const int bh = blockIdx.x;
    const int tid = threadIdx.x;
    float run[16];
#pragma unroll
    for (int i = 0; i < 16; i++) run[i] = 0.f;

    const size_t base = (size_t)bh * NC * (DK * DV);
    for (int c = 0; c < NC; c++) {
        const size_t off = base + (size_t)c * (DK * DV);
#pragma unroll
        for (int i = 0; i < 16; i++) {
            const int idx = i * 256 + tid;
            scum[off + idx] = run[i];
            run[i] += kv[off + idx];
        }
    }
    const size_t tb = (size_t)bh * (DK * DV);
#pragma unroll
    for (int i = 0; i < 16; i++) stot[tb + i * 256 + tid] = run[i];
}

// ---------------------------------------------------------------------------
// Phase C: o = tril(q k^T) v + q (S0[h] + Scum[hk,c]), emitted as hi/lo bf16
// ---------------------------------------------------------------------------
__global__ __launch_bounds__(256)
void attn_kernel(const float* __restrict__ proj, const float* __restrict__ s0,
                 const float* __restrict__ scum,
                 __nv_bfloat16* __restrict__ o_hi,
                 __nv_bfloat16* __restrict__ o_lo) {
    extern __shared__ float sm[];
    float* qs  = sm;            // [64][64] q
    float* SA  = sm + 4096;     // [64][64] S, then A
    float* kvp = sm + 8192;     // [64][65] k, then v

    const int c = blockIdx.x, h = blockIdx.y, b = blockIdx.z;
    const int hk = h >> 2;
    const int tid = threadIdx.x;
    const int tx = tid & 15, ty = tid >> 4;
    const int row0 = ty * 4, col0 = tx * 4;

    const float* qb  = proj + (size_t)(b * SS + c * CH) * QKV + h * DK;
    const float* kb  = proj + (size_t)(b * SS + c * CH) * QKV + HQ * DK + hk * DK;
    const float* vb  = kb + HK * DK;
    const float* s0b = s0 + (size_t)(b * HH + h) * (DK * DV);
    const float* scb = scum + (size_t)((b * HK + hk) * NC + c) * (DK * DV);

    for (int t = tid; t < 1024; t += 256) {
        const int r = t >> 4, c4 = (t & 15) << 2;
        *(float4*)&qs[r * 64 + c4] = *(const float4*)(qb + (size_t)r * QKV + c4);
        float4 u = *(const float4*)(s0b + r * 64 + c4);
        float4 w = *(const float4*)(scb + r * 64 + c4);
        u.x += w.x; u.y += w.y; u.z += w.z; u.w += w.w;
        *(float4*)&SA[r * 64 + c4] = u;
    }
    __syncthreads();

    float acc[4][4];
#pragma unroll
    for (int i = 0; i < 4; i++)
#pragma unroll
        for (int j = 0; j < 4; j++) acc[i][j] = 0.f;

    for (int d = 0; d < 64; d++) {
        float qr[4], sr[4];
#pragma unroll
        for (int i = 0; i < 4; i++) qr[i] = qs[(row0 + i) * 64 + d];
#pragma unroll
        for (int j = 0; j < 4; j++) sr[j] = SA[d * 64 + col0 + j];
#pragma unroll
        for (int i = 0; i < 4; i++)
#pragma unroll
            for (int j = 0; j < 4; j++)
                acc[i][j] = fmaf(qr[i], sr[j], acc[i][j]);
    }

    for (int t = tid; t < 1024; t += 256) {
        const int r = t >> 4, c4 = (t & 15) << 2;
        float4 u = *(const float4*)(kb + (size_t)r * QKV + c4);
        kvp[r * 65 + c4 + 0] = u.x;
        kvp[r * 65 + c4 + 1] = u.y;
        kvp[r * 65 + c4 + 2] = u.z;
        kvp[r * 65 + c4 + 3] = u.w;
    }
    __syncthreads();

    {
        float a[4][4];
#pragma unroll
        for (int i = 0; i < 4; i++)
#pragma unroll
            for (int j = 0; j < 4; j++) a[i][j] = 0.f;
        for (int d = 0; d < 64; d++) {
            float qr[4], kr[4];
#pragma unroll
            for (int i = 0; i < 4; i++) qr[i] = qs[(row0 + i) * 64 + d];
#pragma unroll
            for (int j = 0; j < 4; j++) kr[j] = kvp[(col0 + j) * 65 + d];
#pragma unroll
            for (int i = 0; i < 4; i++)
#pragma unroll
                for (int j = 0; j < 4; j++)
                    a[i][j] = fmaf(qr[i], kr[j], a[i][j]);
        }
#pragma unroll
        for (int i = 0; i < 4; i++)
#pragma unroll
            for (int j = 0; j < 4; j++)
                SA[(row0 + i) * 64 + col0 + j] =
                    (col0 + j <= row0 + i) ? a[i][j] : 0.f;
    }
    __syncthreads();

    for (int t = tid; t < 1024; t += 256) {
        const int r = t >> 4, c4 = (t & 15) << 2;
        float4 u = *(const float4*)(vb + (size_t)r * QKV + c4);
        kvp[r * 65 + c4 + 0] = u.x;
        kvp[r * 65 + c4 + 1] = u.y;
        kvp[r * 65 + c4 + 2] = u.z;
        kvp[r * 65 + c4 + 3] = u.w;
    }
    __syncthreads();

    for (int j = 0; j < 64; j++) {
        float ar[4], vr[4];
#pragma unroll
        for (int i = 0; i < 4; i++) ar[i] = SA[(row0 + i) * 64 + j];
#pragma unroll
        for (int e = 0; e < 4; e++) vr[e] = kvp[j * 65 + col0 + e];
#pragma unroll
        for (int i = 0; i < 4; i++)
#pragma unroll
            for (int e = 0; e < 4; e++)
                acc[i][e] = fmaf(ar[i], vr[e], acc[i][e]);
    }

    const size_t obase = (size_t)(b * SS + c * CH) * (HH * DV) + h * DV;
#pragma unroll
    for (int i = 0; i < 4; i++) {
        __nv_bfloat16 h0, h1, h2, h3, l0, l1, l2, l3;
        split2(acc[i][0], h0, l0); split2(acc[i][1], h1, l1);
        split2(acc[i][2], h2, l2); split2(acc[i][3], h3, l3);
        const size_t r = obase + (size_t)(row0 + i) * (HH * DV) + col0;
        *(__nv_bfloat162*)(o_hi + r)     = __halves2bfloat162(h0, h1);
        *(__nv_bfloat162*)(o_hi + r + 2) = __halves2bfloat162(h2, h3);
        *(__nv_bfloat162*)(o_lo + r)     = __halves2bfloat162(l0, l1);
        *(__nv_bfloat162*)(o_lo + r + 2) = __halves2bfloat162(l2, l3);
    }
}

// ---------------------------------------------------------------------------
// Final state: Sf[b,h] = S0[b,h] + sum_c KV[b, h/4, c]
// ---------------------------------------------------------------------------
__global__ __launch_bounds__(256)
void final_state_kernel(const float* __restrict__ s0,
                        const float* __restrict__ stot,
                        float* __restrict__ out_tail) {
    const int idx = blockIdx.x * 256 + threadIdx.x;
    const int b = idx >> 17;
    const int rem = idx & 131071;
    const int h = rem >> 12;
    const int de = rem & 4095;
    out_tail[idx] = s0[idx] + stot[(size_t)(b * HK + (h >> 2)) * 4096 + de];
}

// ---------------------------------------------------------------------------
extern "C" void kernel_launch(void* const* d_in, const int* in_sizes, int n_in,
                              void* d_out, int out_size) {
    const float* x     = (const float*)d_in[0];   // [B,S,D]
    const float* s0    = (const float*)d_in[1];   // [B,H*DK*DV]
    const float* w_in  = (const float*)d_in[2];   // [D,QKV]
    const float* w_out = (const float*)d_in[3];   // [H*DV,OUT]
    float* out = (float*)d_out;

    float *proj, *kv, *scum, *stot;
    __nv_bfloat16 *x_hi, *x_lo, *winT_hi, *winT_lo, *woutT_hi, *woutT_lo, *o_hi, *o_lo;
    cudaGetSymbolAddress((void**)&proj, g_proj);
    cudaGetSymbolAddress((void**)&kv,   g_kv);
    cudaGetSymbolAddress((void**)&scum, g_scum);
    cudaGetSymbolAddress((void**)&stot, g_stot);
    cudaGetSymbolAddress((void**)&x_hi, g_x_hi);
    cudaGetSymbolAddress((void**)&x_lo, g_x_lo);
    cudaGetSymbolAddress((void**)&winT_hi, g_winT_hi);
    cudaGetSymbolAddress((void**)&winT_lo, g_winT_lo);
    cudaGetSymbolAddress((void**)&woutT_hi, g_woutT_hi);
    cudaGetSymbolAddress((void**)&woutT_lo, g_woutT_lo);
    cudaGetSymbolAddress((void**)&o_hi, g_o_hi);
    cudaGetSymbolAddress((void**)&o_lo, g_o_lo);

    cudaFuncSetAttribute(gemm_mma,
                         cudaFuncAttributeMaxDynamicSharedMemorySize, MMA_SMEM);
    cudaFuncSetAttribute(attn_kernel,
                         cudaFuncAttributeMaxDynamicSharedMemorySize, 49408);

    const dim3 blk(256);

    // 0) input conversions
    convert_split<<<4096, blk>>>((const float4*)x, (__nv_bfloat162*)x_hi,
                                 (__nv_bfloat162*)x_lo, (BB * SS * DD) / 4);
    transpose_split<<<dim3(QKV / 32, DD / 32), dim3(32, 8)>>>(w_in, winT_hi, winT_lo,
                                                              DD, QKV);
    transpose_split<<<dim3(OUT_D / 32, (HH * DV) / 32), dim3(32, 8)>>>(
        w_out, woutT_hi, woutT_lo, HH * DV, OUT_D);

    // 1) proj = x @ W_in  (mma.sync split-bf16)
    gemm_mma<<<dim3(QKV / BN, (BB * SS) / BM), blk, MMA_SMEM>>>(
        x_hi, x_lo, winT_hi, winT_lo, proj, BB * SS, QKV, DD);

    // 2) per-chunk KV
    kv_kernel<<<dim3(NC, HK, BB), blk>>>(proj, kv);

    // 3) exclusive prefix scan
    scan_kernel<<<dim3(BB * HK), blk>>>(kv, scum, stot);

    // 4) per-chunk outputs -> o_hi/o_lo bf16
    attn_kernel<<<dim3(NC, HH, BB), blk, 49408>>>(proj, s0, scum, o_hi, o_lo);

    // 5) out = o @ W_out  (mma.sync split-bf16)
    gemm_mma<<<dim3(OUT_D / BN, (BB * SS) / BM), blk, MMA_SMEM>>>(
        o_hi, o_lo, woutT_hi, woutT_lo, out, BB * SS, OUT_D, HH * DV);

    // 6) final state -> tail of d_out
    final_state_kernel<<<dim3((BB * HH * DK * DV) / 256), blk>>>(
        s0, stot, out + (size_t)BB * SS * OUT_D);
}